// round 14
// baseline (speedup 1.0000x reference)
#include <cuda_runtime.h>
#include <math.h>
#include <stdint.h>

#define NI 16
#define CD 1024
#define PD 1024
#define KC 32
#define EPSN 1e-12f

// ---- scratch (static; no allocations allowed) ----
__device__ float g_ar[NI * KC * PD];     // softmax(a)*r  (kb's B operand)
__device__ float g_asp[NI * KC * 32];    // asum partials (ptile x warp)
__device__ float g_rsp[NI * 8 * KC];     // rowsq partials (ctile x k)
__device__ float g_sc[NI * KC];          // final per-row scale
__device__ unsigned g_ctr[NI];           // ticket 1 (rowsq partials done)
__device__ unsigned g_ctr2[NI];          // ticket 2 (output written)
__device__ unsigned g_flag[NI];          // sc ready

__device__ __forceinline__ uint32_t s2u(const void* p) {
    uint32_t a;
    asm("{ .reg .u64 t; cvta.to.shared.u64 t, %1; cvt.u32.u64 %0, t; }" : "=r"(a) : "l"(p));
    return a;
}

#define CPA16(d, s) asm volatile("cp.async.cg.shared.global [%0], [%1], 16;" :: "r"(d), "l"(s))
#define CPC()  asm volatile("cp.async.commit_group;")
#define CPW1() asm volatile("cp.async.wait_group 1;")
#define CPW0() asm volatile("cp.async.wait_group 0;")

// tf32 m16n8k8 row.col: D += A*B  (A: 4 regs, B: 2 regs, D: 4 floats)
__device__ __forceinline__ void mma8(float* d, const uint32_t* a, const uint32_t* b) {
    asm volatile(
        "mma.sync.aligned.m16n8k8.row.col.f32.tf32.tf32.f32 "
        "{%0,%1,%2,%3}, {%4,%5,%6,%7}, {%8,%9}, {%0,%1,%2,%3};"
        : "+f"(d[0]), "+f"(d[1]), "+f"(d[2]), "+f"(d[3])
        : "r"(a[0]), "r"(a[1]), "r"(a[2]), "r"(a[3]), "r"(b[0]), "r"(b[1]));
}

__device__ __forceinline__ float wred(float s) {
    s += __shfl_xor_sync(0xffffffffu, s, 16);
    s += __shfl_xor_sync(0xffffffffu, s, 8);
    s += __shfl_xor_sync(0xffffffffu, s, 4);
    s += __shfl_xor_sync(0xffffffffu, s, 2);
    s += __shfl_xor_sync(0xffffffffu, s, 1);
    return s;
}

// =====================================================================
// ka: logits GEMM + per-pixel norm + softmax, fused.  (unchanged)
//   D[k=32, p=128] = sum_c w[k,c] * x[c,p]
//   grid (8 ptiles, 16 n), 256 threads = 2 warpgroups (c-split).
// =====================================================================
#define KA_XSF 4352              // 32*136 floats per buffer
#define KA_WSF 1152              // 32*36 floats per buffer
#define KA_SMEM ((4 * KA_XSF + 4 * KA_WSF) * 4)

__global__ void __launch_bounds__(256, 1) ka(const float* __restrict__ x,
                                             const float* __restrict__ w) {
    extern __shared__ float sm[];
    __shared__ float ssqs[128];
    const int tid = threadIdx.x;
    const int wg = tid >> 7, wtid = tid & 127;
    const int lane = tid & 31, wp = wtid >> 5;
    const int qid = lane >> 2, qlane = lane & 3;
    const int ptile = blockIdx.x, n = blockIdx.y, pbase = ptile * 128;
    const float* xn = x + (size_t)n * CD * PD + pbase;
    const uint32_t smu = s2u(sm);

    float d[2][4][4];
#pragma unroll
    for (int mi = 0; mi < 2; mi++)
#pragma unroll
        for (int ni = 0; ni < 4; ni++)
#pragma unroll
            for (int r = 0; r < 4; r++) d[mi][ni][r] = 0.f;
    float ssq = 0.f;

#define KA_LD(gch, buf) do { \
        const float* _x = xn + (size_t)(gch) * 32 * PD; \
        uint32_t _xd = smu + (unsigned)((wg * 2 + (buf)) * KA_XSF) * 4u; \
        _Pragma("unroll") \
        for (int i = 0; i < 8; i++) { \
            int idx = wtid + i * 128, c = idx >> 5, p4 = idx & 31; \
            CPA16(_xd + (unsigned)(c * 136 + p4 * 4) * 4u, _x + (size_t)c * PD + p4 * 4); \
        } \
        const float* _w = w + (gch) * 32; \
        uint32_t _wd = smu + (unsigned)(4 * KA_XSF + (wg * 2 + (buf)) * KA_WSF) * 4u; \
        _Pragma("unroll") \
        for (int i = 0; i < 2; i++) { \
            int idx = wtid + i * 128, k = idx >> 3, c4 = idx & 7; \
            CPA16(_wd + (unsigned)(k * 36 + c4 * 4) * 4u, _w + (size_t)k * CD + c4 * 4); \
        } \
        CPC(); \
    } while (0)

    KA_LD(wg * 16 + 0, 0);
    KA_LD(wg * 16 + 1, 1);

    for (int ch = 0; ch < 16; ch++) {
        const int buf = ch & 1;
        if (ch < 15) CPW1(); else CPW0();
        __syncthreads();
        const float* xsb = sm + (wg * 2 + buf) * KA_XSF;
        const float* wsb = sm + 4 * KA_XSF + (wg * 2 + buf) * KA_WSF;
#pragma unroll
        for (int c = 0; c < 32; c++) {
            float f = xsb[c * 136 + wtid];
            ssq = fmaf(f, f, ssq);
        }
#pragma unroll
        for (int s = 0; s < 4; s++) {
            uint32_t a[2][4], b[4][2];
            const int c0 = s * 8 + qlane;
#pragma unroll
            for (int mi = 0; mi < 2; mi++) {
                const int r0 = mi * 16 + qid;
                a[mi][0] = __float_as_uint(wsb[r0 * 36 + c0]);
                a[mi][1] = __float_as_uint(wsb[(r0 + 8) * 36 + c0]);
                a[mi][2] = __float_as_uint(wsb[r0 * 36 + c0 + 4]);
                a[mi][3] = __float_as_uint(wsb[(r0 + 8) * 36 + c0 + 4]);
            }
#pragma unroll
            for (int ni = 0; ni < 4; ni++) {
                const int pc = wp * 32 + ni * 8 + qid;
                b[ni][0] = __float_as_uint(xsb[c0 * 136 + pc]);
                b[ni][1] = __float_as_uint(xsb[(c0 + 4) * 136 + pc]);
            }
#pragma unroll
            for (int mi = 0; mi < 2; mi++)
#pragma unroll
                for (int ni = 0; ni < 4; ni++) mma8(d[mi][ni], a[mi], b[ni]);
        }
        __syncthreads();
        if (ch + 2 < 16) KA_LD(wg * 16 + ch + 2, buf);
    }
#undef KA_LD

    // ---- combine wg partial logits in smem: Ls[32 k][136] ----
    float (*Ls)[136] = (float (*)[136])sm;
    if (wg == 1) {
#pragma unroll
        for (int mi = 0; mi < 2; mi++)
#pragma unroll
            for (int ni = 0; ni < 4; ni++) {
                const int px = wp * 32 + ni * 8 + 2 * qlane;
                *(float2*)&Ls[mi * 16 + qid][px] = make_float2(d[mi][ni][0], d[mi][ni][1]);
                *(float2*)&Ls[mi * 16 + qid + 8][px] = make_float2(d[mi][ni][2], d[mi][ni][3]);
            }
        ssqs[wtid] = ssq;
    }
    __syncthreads();
    if (wg == 0) {
#pragma unroll
        for (int mi = 0; mi < 2; mi++)
#pragma unroll
            for (int ni = 0; ni < 4; ni++) {
                const int px = wp * 32 + ni * 8 + 2 * qlane;
                float2 u = *(float2*)&Ls[mi * 16 + qid][px];
                u.x += d[mi][ni][0]; u.y += d[mi][ni][1];
                *(float2*)&Ls[mi * 16 + qid][px] = u;
                float2 v = *(float2*)&Ls[mi * 16 + qid + 8][px];
                v.x += d[mi][ni][2]; v.y += d[mi][ni][3];
                *(float2*)&Ls[mi * 16 + qid + 8][px] = v;
            }
    }
    __syncthreads();

    // ---- softmax: wg0 thread owns pixel wtid ----
    if (wg == 0) {
        ssq += ssqs[wtid];
        const float r = 1.f / fmaxf(sqrtf(ssq), EPSN);
        float L[KC], m = -1e30f;
#pragma unroll
        for (int k = 0; k < KC; k++) {
            L[k] = Ls[k][wtid] * r;
            m = fmaxf(m, L[k]);
        }
        float ssum = 0.f;
#pragma unroll
        for (int k = 0; k < KC; k++) {
            L[k] = __expf(L[k] - m);
            ssum += L[k];
        }
        const float inv = 1.f / ssum;
        float* arp = g_ar + (size_t)n * KC * PD + pbase + wtid;
#pragma unroll
        for (int k = 0; k < KC; k++) {
            float a = L[k] * inv;
            arp[(size_t)k * PD] = a * r;
            float t = wred(a);
            if (lane == 0) g_asp[(n * KC + k) * 32 + ptile * 4 + wp] = t;
        }
    }
}

// =====================================================================
// kb: vlad GEMM + register-resident epilogue.
//   D[c=128, k=32] = sum_p x[c,p] * ar[k,p]
//   grid (8 ctiles, 16 n), 512 threads = 4 warpgroups (c-split!).
//   wg owns 32 c rows over ALL p; chunks = [32c x 128p] (512B rows).
//   ar chunk loaded once per block, shared by all wgs.
// =====================================================================
#define KB_XSF 4224              // 32*132 floats per x buffer
#define KB_ASF 4224              // 32*132 floats per ar buffer
#define KB_AOFF (8 * KB_XSF)     // ar region start (floats)
#define KB_SMEM ((8 * KB_XSF + 2 * KB_ASF) * 4)   // 168960 B

__global__ void __launch_bounds__(512, 1) kb(const float* __restrict__ x,
                                             const float* __restrict__ cent,
                                             float* __restrict__ out) {
    extern __shared__ float sm[];
    __shared__ float s_asum[32], s_sc2[32], srq[8][32];
    __shared__ unsigned s_old;
    const int tid = threadIdx.x;
    const int wg = tid >> 7, wtid = tid & 127;
    const int lane = tid & 31, wp = wtid >> 5;
    const int qid = lane >> 2, qlane = lane & 3;
    const int wp_c = wp & 1, wp_k = wp >> 1;
    const int ctile = blockIdx.x, n = blockIdx.y, cbase = ctile * 128;
    const float* xn = x + ((size_t)n * CD + cbase + wg * 32) * PD;  // this wg's 32 c rows
    const float* arn = g_ar + (size_t)n * KC * PD;
    const uint32_t smu = s2u(sm);

    // asum for this image (g_asp complete: previous launch)
    if (tid < 32) {
        float t = 0.f;
#pragma unroll
        for (int i = 0; i < 32; i++) t += g_asp[(n * KC + tid) * 32 + i];
        s_asum[tid] = t;
    }

    float d[2][4];                      // [ni (k8)][frag]
#pragma unroll
    for (int ni = 0; ni < 2; ni++)
#pragma unroll
        for (int r = 0; r < 4; r++) d[ni][r] = 0.f;

#define KB_LD(ch, buf) do { \
        const int _p0 = (ch) * 128; \
        uint32_t _xd = smu + (unsigned)((wg * 2 + (buf)) * KB_XSF) * 4u; \
        _Pragma("unroll") \
        for (int i = 0; i < 8; i++) { \
            int idx = wtid + i * 128, c = idx >> 5, p4 = idx & 31; \
            CPA16(_xd + (unsigned)(c * 132 + p4 * 4) * 4u, xn + (size_t)c * PD + _p0 + p4 * 4); \
        } \
        uint32_t _ad = smu + (unsigned)(KB_AOFF + (buf) * KB_ASF) * 4u; \
        _Pragma("unroll") \
        for (int i = 0; i < 2; i++) { \
            int idx = tid + i * 512, k = idx >> 5, p4 = idx & 31; \
            CPA16(_ad + (unsigned)(k * 132 + p4 * 4) * 4u, arn + (size_t)k * PD + _p0 + p4 * 4); \
        } \
        CPC(); \
    } while (0)

    KB_LD(0, 0);
    KB_LD(1, 1);

    for (int ch = 0; ch < 8; ch++) {
        const int buf = ch & 1;
        if (ch < 7) CPW1(); else CPW0();
        __syncthreads();
        const float* xsb = sm + (wg * 2 + buf) * KB_XSF;
        const float* asb = sm + KB_AOFF + buf * KB_ASF;
#pragma unroll
        for (int s = 0; s < 16; s++) {
            const int p0 = s * 8 + qlane;
            uint32_t a[4], b[2][2];
            const int r0 = wp_c * 16 + qid;
            a[0] = __float_as_uint(xsb[r0 * 132 + p0]);
            a[1] = __float_as_uint(xsb[(r0 + 8) * 132 + p0]);
            a[2] = __float_as_uint(xsb[r0 * 132 + p0 + 4]);
            a[3] = __float_as_uint(xsb[(r0 + 8) * 132 + p0 + 4]);
#pragma unroll
            for (int ni = 0; ni < 2; ni++) {
                const int kk = wp_k * 16 + ni * 8 + qid;
                b[ni][0] = __float_as_uint(asb[kk * 132 + p0]);
                b[ni][1] = __float_as_uint(asb[kk * 132 + p0 + 4]);
            }
#pragma unroll
            for (int ni = 0; ni < 2; ni++) mma8(d[ni], a, b[ni]);
        }
        __syncthreads();
        if (ch + 2 < 8) KB_LD(ch + 2, buf);
    }
#undef KB_LD

    // no cross-wg combine needed: each wg's D slice is complete.
    __syncthreads();

    // ---- stage centroid tile cs[32 k][132] (aliases x smem region) ----
    float* cs = sm;
    for (int i = tid; i < 32 * 128; i += 512) {
        int k = i >> 7, cc = i & 127;
        cs[k * 132 + cc] = cent[k * CD + cbase + cc];
    }
    __syncthreads();

    // ---- subtract asum*cent in regs + rowsq partials ----
    {
        const int cl = wg * 32 + wp_c * 16 + qid;   // block-local c of frag rows 0/1
        float rq[2][2];
#pragma unroll
        for (int ni = 0; ni < 2; ni++) { rq[ni][0] = 0.f; rq[ni][1] = 0.f; }
#pragma unroll
        for (int ni = 0; ni < 2; ni++) {
            const int k0 = wp_k * 16 + ni * 8 + 2 * qlane;
            const float as0 = s_asum[k0], as1 = s_asum[k0 + 1];
            d[ni][0] -= as0 * cs[k0 * 132 + cl];
            d[ni][1] -= as1 * cs[(k0 + 1) * 132 + cl];
            d[ni][2] -= as0 * cs[k0 * 132 + cl + 8];
            d[ni][3] -= as1 * cs[(k0 + 1) * 132 + cl + 8];
            rq[ni][0] += d[ni][0] * d[ni][0] + d[ni][2] * d[ni][2];
            rq[ni][1] += d[ni][1] * d[ni][1] + d[ni][3] * d[ni][3];
        }
        // reduce over qid (c direction) within warp; group = (wg, wp_c)
#pragma unroll
        for (int ni = 0; ni < 2; ni++)
#pragma unroll
            for (int b = 0; b < 2; b++) {
                float s = rq[ni][b];
                s += __shfl_xor_sync(0xffffffffu, s, 4);
                s += __shfl_xor_sync(0xffffffffu, s, 8);
                s += __shfl_xor_sync(0xffffffffu, s, 16);
                if (qid == 0)
                    srq[wg * 2 + wp_c][wp_k * 16 + ni * 8 + 2 * qlane + b] = s;
            }
    }
    __syncthreads();
    if (tid < 32) {
        float pr = 0.f;
#pragma unroll
        for (int g = 0; g < 8; g++) pr += srq[g][tid];
        g_rsp[(n * 8 + ctile) * 32 + tid] = pr;
    }
    __syncthreads();
    if (tid == 0) {
        __threadfence();
        s_old = atomicAdd(&g_ctr[n], 1u);
    }
    __syncthreads();

    if (s_old == 7u) {
        __threadfence();
        if (tid < 32) {
            float tot = 0.f;
#pragma unroll
            for (int ct = 0; ct < 8; ct++) tot += g_rsp[(n * 8 + ct) * 32 + tid];
            float ri = 1.f / fmaxf(sqrtf(tot), EPSN);
            float gg = wred(tot * ri * ri);
            g_sc[n * 32 + tid] = ri * (1.f / fmaxf(sqrtf(gg), EPSN));
        }
        __syncthreads();
        if (tid == 0) {
            __threadfence();
            atomicExch(&g_flag[n], 1u);
        }
    }

    // spin for sc (all 128 blocks resident: 1 CTA/SM, 148 SMs -> safe)
    if (tid == 0) {
        while (atomicOr(&g_flag[n], 0u) == 0u) __nanosleep(64);
        __threadfence();
    }
    __syncthreads();
    if (tid < 32) s_sc2[tid] = g_sc[n * 32 + tid];
    __syncthreads();

    // ---- scale register tile and write out ----
    {
        const int cg = cbase + wg * 32 + wp_c * 16 + qid;
        float* on = out + (size_t)n * KC * CD;
#pragma unroll
        for (int ni = 0; ni < 2; ni++) {
            const int k0 = wp_k * 16 + ni * 8 + 2 * qlane;
            const float sc0 = s_sc2[k0], sc1 = s_sc2[k0 + 1];
            on[(size_t)k0 * CD + cg] = d[ni][0] * sc0;
            on[(size_t)(k0 + 1) * CD + cg] = d[ni][1] * sc1;
            on[(size_t)k0 * CD + cg + 8] = d[ni][2] * sc0;
            on[(size_t)(k0 + 1) * CD + cg + 8] = d[ni][3] * sc1;
        }
    }
    __syncthreads();
    if (tid == 0) {
        unsigned o2 = atomicAdd(&g_ctr2[n], 1u);
        if (o2 == 7u) {   // all 8 blocks done: reset for next replay
            g_flag[n] = 0u;
            g_ctr[n] = 0u;
            g_ctr2[n] = 0u;
        }
    }
}

extern "C" void kernel_launch(void* const* d_in, const int* in_sizes, int n_in,
                              void* d_out, int out_size) {
    const float* x = (const float*)d_in[0];     // (16,1024,32,32)
    const float* w = (const float*)d_in[1];     // (32,1024)
    const float* cent = (const float*)d_in[2];  // (32,1024)
    float* out = (float*)d_out;                 // (16,32768)

    static int inited = 0;
    if (!inited) {
        cudaFuncSetAttribute(ka, cudaFuncAttributeMaxDynamicSharedMemorySize, KA_SMEM);
        cudaFuncSetAttribute(kb, cudaFuncAttributeMaxDynamicSharedMemorySize, KB_SMEM);
        inited = 1;
    }

    ka<<<dim3(8, 16), 256, KA_SMEM>>>(x, w);
    kb<<<dim3(8, 16), 512, KB_SMEM>>>(x, cent, out);
}

// round 16
// speedup vs baseline: 1.0156x; 1.0156x over previous
#include <cuda_runtime.h>
#include <math.h>
#include <stdint.h>

#define NI 16
#define CD 1024
#define PD 1024
#define KC 32
#define EPSN 1e-12f

// ---- scratch (static; no allocations allowed) ----
__device__ float g_ar[NI * KC * PD];     // softmax(a)*r  (kb's B operand)
__device__ float g_asp[NI * KC * 32];    // asum partials (ptile x warp)
__device__ float g_rsp[NI * 8 * KC];     // rowsq partials (ctile x k)
__device__ float g_sc[NI * KC];          // final per-row scale
__device__ unsigned g_ctr[NI];           // ticket 1 (rowsq partials done)
__device__ unsigned g_ctr2[NI];          // ticket 2 (output written)
__device__ unsigned g_flag[NI];          // sc ready

__device__ __forceinline__ uint32_t s2u(const void* p) {
    uint32_t a;
    asm("{ .reg .u64 t; cvta.to.shared.u64 t, %1; cvt.u32.u64 %0, t; }" : "=r"(a) : "l"(p));
    return a;
}

#define CPA16(d, s) asm volatile("cp.async.cg.shared.global [%0], [%1], 16;" :: "r"(d), "l"(s))
#define CPC()  asm volatile("cp.async.commit_group;")
#define CPW1() asm volatile("cp.async.wait_group 1;")
#define CPW0() asm volatile("cp.async.wait_group 0;")

// tf32 m16n8k8 row.col: D += A*B  (A: 4 regs, B: 2 regs, D: 4 floats)
__device__ __forceinline__ void mma8(float* d, const uint32_t* a, const uint32_t* b) {
    asm volatile(
        "mma.sync.aligned.m16n8k8.row.col.f32.tf32.tf32.f32 "
        "{%0,%1,%2,%3}, {%4,%5,%6,%7}, {%8,%9}, {%0,%1,%2,%3};"
        : "+f"(d[0]), "+f"(d[1]), "+f"(d[2]), "+f"(d[3])
        : "r"(a[0]), "r"(a[1]), "r"(a[2]), "r"(a[3]), "r"(b[0]), "r"(b[1]));
}

__device__ __forceinline__ float wred(float s) {
    s += __shfl_xor_sync(0xffffffffu, s, 16);
    s += __shfl_xor_sync(0xffffffffu, s, 8);
    s += __shfl_xor_sync(0xffffffffu, s, 4);
    s += __shfl_xor_sync(0xffffffffu, s, 2);
    s += __shfl_xor_sync(0xffffffffu, s, 1);
    return s;
}

// =====================================================================
// ka: logits GEMM + per-pixel norm + softmax, fused.  (unchanged)
//   D[k=32, p=128] = sum_c w[k,c] * x[c,p]
//   grid (8 ptiles, 16 n), 256 threads = 2 warpgroups (c-split).
// =====================================================================
#define KA_XSF 4352              // 32*136 floats per buffer
#define KA_WSF 1152              // 32*36 floats per buffer
#define KA_SMEM ((4 * KA_XSF + 4 * KA_WSF) * 4)

__global__ void __launch_bounds__(256, 1) ka(const float* __restrict__ x,
                                             const float* __restrict__ w) {
    extern __shared__ float sm[];
    __shared__ float ssqs[128];
    const int tid = threadIdx.x;
    const int wg = tid >> 7, wtid = tid & 127;
    const int lane = tid & 31, wp = wtid >> 5;
    const int qid = lane >> 2, qlane = lane & 3;
    const int ptile = blockIdx.x, n = blockIdx.y, pbase = ptile * 128;
    const float* xn = x + (size_t)n * CD * PD + pbase;
    const uint32_t smu = s2u(sm);

    float d[2][4][4];
#pragma unroll
    for (int mi = 0; mi < 2; mi++)
#pragma unroll
        for (int ni = 0; ni < 4; ni++)
#pragma unroll
            for (int r = 0; r < 4; r++) d[mi][ni][r] = 0.f;
    float ssq = 0.f;

#define KA_LD(gch, buf) do { \
        const float* _x = xn + (size_t)(gch) * 32 * PD; \
        uint32_t _xd = smu + (unsigned)((wg * 2 + (buf)) * KA_XSF) * 4u; \
        _Pragma("unroll") \
        for (int i = 0; i < 8; i++) { \
            int idx = wtid + i * 128, c = idx >> 5, p4 = idx & 31; \
            CPA16(_xd + (unsigned)(c * 136 + p4 * 4) * 4u, _x + (size_t)c * PD + p4 * 4); \
        } \
        const float* _w = w + (gch) * 32; \
        uint32_t _wd = smu + (unsigned)(4 * KA_XSF + (wg * 2 + (buf)) * KA_WSF) * 4u; \
        _Pragma("unroll") \
        for (int i = 0; i < 2; i++) { \
            int idx = wtid + i * 128, k = idx >> 3, c4 = idx & 7; \
            CPA16(_wd + (unsigned)(k * 36 + c4 * 4) * 4u, _w + (size_t)k * CD + c4 * 4); \
        } \
        CPC(); \
    } while (0)

    KA_LD(wg * 16 + 0, 0);
    KA_LD(wg * 16 + 1, 1);

    for (int ch = 0; ch < 16; ch++) {
        const int buf = ch & 1;
        if (ch < 15) CPW1(); else CPW0();
        __syncthreads();
        const float* xsb = sm + (wg * 2 + buf) * KA_XSF;
        const float* wsb = sm + 4 * KA_XSF + (wg * 2 + buf) * KA_WSF;
#pragma unroll
        for (int c = 0; c < 32; c++) {
            float f = xsb[c * 136 + wtid];
            ssq = fmaf(f, f, ssq);
        }
#pragma unroll
        for (int s = 0; s < 4; s++) {
            uint32_t a[2][4], b[4][2];
            const int c0 = s * 8 + qlane;
#pragma unroll
            for (int mi = 0; mi < 2; mi++) {
                const int r0 = mi * 16 + qid;
                a[mi][0] = __float_as_uint(wsb[r0 * 36 + c0]);
                a[mi][1] = __float_as_uint(wsb[(r0 + 8) * 36 + c0]);
                a[mi][2] = __float_as_uint(wsb[r0 * 36 + c0 + 4]);
                a[mi][3] = __float_as_uint(wsb[(r0 + 8) * 36 + c0 + 4]);
            }
#pragma unroll
            for (int ni = 0; ni < 4; ni++) {
                const int pc = wp * 32 + ni * 8 + qid;
                b[ni][0] = __float_as_uint(xsb[c0 * 136 + pc]);
                b[ni][1] = __float_as_uint(xsb[(c0 + 4) * 136 + pc]);
            }
#pragma unroll
            for (int mi = 0; mi < 2; mi++)
#pragma unroll
                for (int ni = 0; ni < 4; ni++) mma8(d[mi][ni], a[mi], b[ni]);
        }
        __syncthreads();
        if (ch + 2 < 16) KA_LD(wg * 16 + ch + 2, buf);
    }
#undef KA_LD

    // ---- combine wg partial logits in smem: Ls[32 k][136] ----
    float (*Ls)[136] = (float (*)[136])sm;
    if (wg == 1) {
#pragma unroll
        for (int mi = 0; mi < 2; mi++)
#pragma unroll
            for (int ni = 0; ni < 4; ni++) {
                const int px = wp * 32 + ni * 8 + 2 * qlane;
                *(float2*)&Ls[mi * 16 + qid][px] = make_float2(d[mi][ni][0], d[mi][ni][1]);
                *(float2*)&Ls[mi * 16 + qid + 8][px] = make_float2(d[mi][ni][2], d[mi][ni][3]);
            }
        ssqs[wtid] = ssq;
    }
    __syncthreads();
    if (wg == 0) {
#pragma unroll
        for (int mi = 0; mi < 2; mi++)
#pragma unroll
            for (int ni = 0; ni < 4; ni++) {
                const int px = wp * 32 + ni * 8 + 2 * qlane;
                float2 u = *(float2*)&Ls[mi * 16 + qid][px];
                u.x += d[mi][ni][0]; u.y += d[mi][ni][1];
                *(float2*)&Ls[mi * 16 + qid][px] = u;
                float2 v = *(float2*)&Ls[mi * 16 + qid + 8][px];
                v.x += d[mi][ni][2]; v.y += d[mi][ni][3];
                *(float2*)&Ls[mi * 16 + qid + 8][px] = v;
            }
    }
    __syncthreads();

    // ---- softmax: wg0 thread owns pixel wtid ----
    if (wg == 0) {
        ssq += ssqs[wtid];
        const float r = 1.f / fmaxf(sqrtf(ssq), EPSN);
        float L[KC], m = -1e30f;
#pragma unroll
        for (int k = 0; k < KC; k++) {
            L[k] = Ls[k][wtid] * r;
            m = fmaxf(m, L[k]);
        }
        float ssum = 0.f;
#pragma unroll
        for (int k = 0; k < KC; k++) {
            L[k] = __expf(L[k] - m);
            ssum += L[k];
        }
        const float inv = 1.f / ssum;
        float* arp = g_ar + (size_t)n * KC * PD + pbase + wtid;
#pragma unroll
        for (int k = 0; k < KC; k++) {
            float a = L[k] * inv;
            arp[(size_t)k * PD] = a * r;
            float t = wred(a);
            if (lane == 0) g_asp[(n * KC + k) * 32 + ptile * 4 + wp] = t;
        }
    }
}

// =====================================================================
// kb: vlad GEMM + register-resident epilogue.
//   D[c=128, k=32] = sum_p x[c,p] * ar[k,p]
//   grid (8 ctiles, 16 n), 512 threads = 4 wgs (c-split).
//   Within a wg, the 4 warps split the 16 p-steps (4 each); each warp
//   computes the FULL m32 x n32 tile (8 MMAs/step, 2.0 LDS/MMA).
//   Cross-warp p-partials combined once in smem at the end.
// =====================================================================
#define KB_XSF 4224              // 32*132 floats per x buffer
#define KB_ASF 4224              // 32*132 floats per ar buffer
#define KB_AOFF (8 * KB_XSF)     // ar region start (floats)
#define KB_SMEM ((8 * KB_XSF + 2 * KB_ASF) * 4)   // 168960 B
#define KB_DUMPF 1088            // 32*34 floats per dump region (EVEN stride!)
#define KB_CSOFF (12 * KB_DUMPF) // centroid tile offset = 13056 floats

__global__ void __launch_bounds__(512, 1) kb(const float* __restrict__ x,
                                             const float* __restrict__ cent,
                                             float* __restrict__ out) {
    extern __shared__ float sm[];
    __shared__ float s_asum[32], s_sc2[32], srq[4][32];
    __shared__ unsigned s_old;
    const int tid = threadIdx.x;
    const int wg = tid >> 7, wtid = tid & 127;
    const int lane = tid & 31, wq = wtid >> 5;
    const int qid = lane >> 2, qlane = lane & 3;
    const int ctile = blockIdx.x, n = blockIdx.y, cbase = ctile * 128;
    const float* xn = x + ((size_t)n * CD + cbase + wg * 32) * PD;  // this wg's 32 c rows
    const float* arn = g_ar + (size_t)n * KC * PD;
    const uint32_t smu = s2u(sm);

    // asum for this image (g_asp complete: previous launch)
    if (tid < 32) {
        float t = 0.f;
#pragma unroll
        for (int i = 0; i < 32; i++) t += g_asp[(n * KC + tid) * 32 + i];
        s_asum[tid] = t;
    }

    float d[2][4][4];                   // [mi c16][ni k8][frag]
#pragma unroll
    for (int mi = 0; mi < 2; mi++)
#pragma unroll
        for (int ni = 0; ni < 4; ni++)
#pragma unroll
            for (int r = 0; r < 4; r++) d[mi][ni][r] = 0.f;

#define KB_LD(ch, buf) do { \
        const int _p0 = (ch) * 128; \
        uint32_t _xd = smu + (unsigned)((wg * 2 + (buf)) * KB_XSF) * 4u; \
        _Pragma("unroll") \
        for (int i = 0; i < 8; i++) { \
            int idx = wtid + i * 128, c = idx >> 5, p4 = idx & 31; \
            CPA16(_xd + (unsigned)(c * 132 + p4 * 4) * 4u, xn + (size_t)c * PD + _p0 + p4 * 4); \
        } \
        uint32_t _ad = smu + (unsigned)(KB_AOFF + (buf) * KB_ASF) * 4u; \
        _Pragma("unroll") \
        for (int i = 0; i < 2; i++) { \
            int idx = tid + i * 512, k = idx >> 5, p4 = idx & 31; \
            CPA16(_ad + (unsigned)(k * 132 + p4 * 4) * 4u, arn + (size_t)k * PD + _p0 + p4 * 4); \
        } \
        CPC(); \
    } while (0)

    KB_LD(0, 0);
    KB_LD(1, 1);

    for (int ch = 0; ch < 8; ch++) {
        const int buf = ch & 1;
        if (ch < 7) CPW1(); else CPW0();
        __syncthreads();
        const float* xsb = sm + (wg * 2 + buf) * KB_XSF;
        const float* asb = sm + KB_AOFF + buf * KB_ASF;
        // warp wq handles p-steps [wq*4, wq*4+4)
#pragma unroll
        for (int j = 0; j < 4; j++) {
            const int p0 = (wq * 4 + j) * 8 + qlane;
            uint32_t a[2][4], b[4][2];
#pragma unroll
            for (int mi = 0; mi < 2; mi++) {
                const int r0 = mi * 16 + qid;
                a[mi][0] = __float_as_uint(xsb[r0 * 132 + p0]);
                a[mi][1] = __float_as_uint(xsb[(r0 + 8) * 132 + p0]);
                a[mi][2] = __float_as_uint(xsb[r0 * 132 + p0 + 4]);
                a[mi][3] = __float_as_uint(xsb[(r0 + 8) * 132 + p0 + 4]);
            }
#pragma unroll
            for (int ni = 0; ni < 4; ni++) {
                const int kk = ni * 8 + qid;
                b[ni][0] = __float_as_uint(asb[kk * 132 + p0]);
                b[ni][1] = __float_as_uint(asb[kk * 132 + p0 + 4]);
            }
#pragma unroll
            for (int mi = 0; mi < 2; mi++)
#pragma unroll
                for (int ni = 0; ni < 4; ni++) mma8(d[mi][ni], a[mi], b[ni]);
        }
        __syncthreads();
        if (ch + 2 < 8) KB_LD(ch + 2, buf);
    }
#undef KB_LD

    // ---- combine p-partials across the 4 warps of each wg ----
    // warps 1..3 dump to smem region (wg*3 + wq-1); warp 0 accumulates.
    if (wq != 0) {
        float* Dw = sm + (wg * 3 + (wq - 1)) * KB_DUMPF;   // [32 c][34]
#pragma unroll
        for (int mi = 0; mi < 2; mi++) {
            const int cl = mi * 16 + qid;
#pragma unroll
            for (int ni = 0; ni < 4; ni++) {
                const int k0 = ni * 8 + 2 * qlane;
                *(float2*)&Dw[cl * 34 + k0] = make_float2(d[mi][ni][0], d[mi][ni][1]);
                *(float2*)&Dw[(cl + 8) * 34 + k0] = make_float2(d[mi][ni][2], d[mi][ni][3]);
            }
        }
    }
    __syncthreads();
    if (wq == 0) {
#pragma unroll
        for (int mi = 0; mi < 2; mi++) {
            const int cl = mi * 16 + qid;
#pragma unroll
            for (int ni = 0; ni < 4; ni++) {
                const int k0 = ni * 8 + 2 * qlane;
#pragma unroll
                for (int g = 0; g < 3; g++) {
                    const float* Dw = sm + (wg * 3 + g) * KB_DUMPF;
                    float2 u = *(const float2*)&Dw[cl * 34 + k0];
                    float2 v = *(const float2*)&Dw[(cl + 8) * 34 + k0];
                    d[mi][ni][0] += u.x; d[mi][ni][1] += u.y;
                    d[mi][ni][2] += v.x; d[mi][ni][3] += v.y;
                }
            }
        }
    } else {
        // warps 1..3 stage centroid tile cs[32 k][132] (block c-slice)
        float* cs = sm + KB_CSOFF;
        for (int i = wg * 96 + (wq - 1) * 32 + lane; i < 32 * 128; i += 384) {
            int k = i >> 7, cc = i & 127;
            cs[k * 132 + cc] = cent[k * CD + cbase + cc];
        }
    }
    __syncthreads();

    // ---- subtract asum*cent in regs + rowsq partials (warp0 of each wg) ----
    const float* cs = sm + KB_CSOFF;
    if (wq == 0) {
        float rq[4][2];
#pragma unroll
        for (int ni = 0; ni < 4; ni++) { rq[ni][0] = 0.f; rq[ni][1] = 0.f; }
#pragma unroll
        for (int mi = 0; mi < 2; mi++) {
            const int cl = wg * 32 + mi * 16 + qid;   // block-local c
#pragma unroll
            for (int ni = 0; ni < 4; ni++) {
                const int k0 = ni * 8 + 2 * qlane;
                const float as0 = s_asum[k0], as1 = s_asum[k0 + 1];
                d[mi][ni][0] -= as0 * cs[k0 * 132 + cl];
                d[mi][ni][1] -= as1 * cs[(k0 + 1) * 132 + cl];
                d[mi][ni][2] -= as0 * cs[k0 * 132 + cl + 8];
                d[mi][ni][3] -= as1 * cs[(k0 + 1) * 132 + cl + 8];
                rq[ni][0] += d[mi][ni][0] * d[mi][ni][0] + d[mi][ni][2] * d[mi][ni][2];
                rq[ni][1] += d[mi][ni][1] * d[mi][ni][1] + d[mi][ni][3] * d[mi][ni][3];
            }
        }
        // reduce over qid (c direction) within warp
#pragma unroll
        for (int ni = 0; ni < 4; ni++)
#pragma unroll
            for (int b = 0; b < 2; b++) {
                float s = rq[ni][b];
                s += __shfl_xor_sync(0xffffffffu, s, 4);
                s += __shfl_xor_sync(0xffffffffu, s, 8);
                s += __shfl_xor_sync(0xffffffffu, s, 16);
                if (qid == 0) srq[wg][ni * 8 + 2 * qlane + b] = s;
            }
    }
    __syncthreads();
    if (tid < 32) {
        float pr = srq[0][tid] + srq[1][tid] + srq[2][tid] + srq[3][tid];
        g_rsp[(n * 8 + ctile) * 32 + tid] = pr;
    }
    __syncthreads();
    if (tid == 0) {
        __threadfence();
        s_old = atomicAdd(&g_ctr[n], 1u);
    }
    __syncthreads();

    if (s_old == 7u) {
        __threadfence();
        if (tid < 32) {
            float tot = 0.f;
#pragma unroll
            for (int ct = 0; ct < 8; ct++) tot += g_rsp[(n * 8 + ct) * 32 + tid];
            float ri = 1.f / fmaxf(sqrtf(tot), EPSN);
            float gg = wred(tot * ri * ri);
            g_sc[n * 32 + tid] = ri * (1.f / fmaxf(sqrtf(gg), EPSN));
        }
        __syncthreads();
        if (tid == 0) {
            __threadfence();
            atomicExch(&g_flag[n], 1u);
        }
    }

    // spin for sc (all 128 blocks resident: 1 CTA/SM, 148 SMs -> safe)
    if (tid == 0) {
        while (atomicOr(&g_flag[n], 0u) == 0u) __nanosleep(64);
        __threadfence();
    }
    __syncthreads();
    if (tid < 32) s_sc2[tid] = g_sc[n * 32 + tid];
    __syncthreads();

    // ---- scale register tile and write out (warp0 of each wg) ----
    if (wq == 0) {
        float* on = out + (size_t)n * KC * CD;
#pragma unroll
        for (int mi = 0; mi < 2; mi++) {
            const int cg = cbase + wg * 32 + mi * 16 + qid;
#pragma unroll
            for (int ni = 0; ni < 4; ni++) {
                const int k0 = ni * 8 + 2 * qlane;
                const float sc0 = s_sc2[k0], sc1 = s_sc2[k0 + 1];
                on[(size_t)k0 * CD + cg] = d[mi][ni][0] * sc0;
                on[(size_t)(k0 + 1) * CD + cg] = d[mi][ni][1] * sc1;
                on[(size_t)k0 * CD + cg + 8] = d[mi][ni][2] * sc0;
                on[(size_t)(k0 + 1) * CD + cg + 8] = d[mi][ni][3] * sc1;
            }
        }
    }
    __syncthreads();
    if (tid == 0) {
        unsigned o2 = atomicAdd(&g_ctr2[n], 1u);
        if (o2 == 7u) {   // all 8 blocks done: reset for next replay
            g_flag[n] = 0u;
            g_ctr[n] = 0u;
            g_ctr2[n] = 0u;
        }
    }
}

extern "C" void kernel_launch(void* const* d_in, const int* in_sizes, int n_in,
                              void* d_out, int out_size) {
    const float* x = (const float*)d_in[0];     // (16,1024,32,32)
    const float* w = (const float*)d_in[1];     // (32,1024)
    const float* cent = (const float*)d_in[2];  // (32,1024)
    float* out = (float*)d_out;                 // (16,32768)

    static int inited = 0;
    if (!inited) {
        cudaFuncSetAttribute(ka, cudaFuncAttributeMaxDynamicSharedMemorySize, KA_SMEM);
        cudaFuncSetAttribute(kb, cudaFuncAttributeMaxDynamicSharedMemorySize, KB_SMEM);
        inited = 1;
    }

    ka<<<dim3(8, 16), 256, KA_SMEM>>>(x, w);
    kb<<<dim3(8, 16), 512, KB_SMEM>>>(x, cent, out);
}